// round 4
// baseline (speedup 1.0000x reference)
#include <cuda_runtime.h>
#include <cuda_fp16.h>
#include <cstdint>

// ImageWarped: trilinear sampling of [B,128,128,128,1] fp32 at [B,N,3] coords.
// B=2, N=2097152.
//
// Phase 1 (pack): per voxel (b,x,y,z) pack the 2x2x2 corner cube as 8 x fp16
//   in one uint4 (64 MB scratch). Vectorized: 4 z-consecutive voxels/thread.
// Phase 2 (sample): ONE scattered LDG.128 per sample. 4 samples/thread for
//   MLP: 3x float4 grid loads, 4 independent uint4 gathers, float4 store.
//
// fp16 corner quantization -> aggregate rel_err ~2e-4 (<1e-3 gate, verified
// in R3). Boundary-clamped "+1" entries are weight-masked (exactly-zero
// fractional weights per the reference floor/ceil convention).

#define BATCH 2
#define NPTS  2097152
#define VOXELS (BATCH * 128 * 128 * 128)   // 4194304
#define CLAMP_LO 0.001f
#define CLAMP_HI 126.999f                  // min(SIZE) - 1.001

__device__ uint4 g_packed[VOXELS];         // 64 MB scratch: 8 fp16 per voxel

__device__ __forceinline__ uint32_t pack_h2(float a, float b) {
    __half2 h = __floats2half2_rn(a, b);
    return *reinterpret_cast<uint32_t*>(&h);
}

// One thread packs 4 voxels (z-quad). Row of 5 floats per (x,y) pair needed.
__global__ void __launch_bounds__(256)
pack_kernel(const float* __restrict__ image)
{
    const int t = blockIdx.x * blockDim.x + threadIdx.x;     // quad id
    const int idx = t << 2;                                  // voxel linear base
    const int zb = idx & 127;                                // 0,4,...,124
    const int y  = (idx >> 7) & 127;
    const int x  = (idx >> 14) & 127;
    const int dy = (y < 127) ? 128 : 0;                      // weight-masked at 127
    const int dx = (x < 127) ? 16384 : 0;

    const int i00 = idx;                 // (x,   y  )
    const int i01 = idx + dy;            // (x,   y+1)
    const int i10 = idx + dx;            // (x+1, y  )
    const int i11 = idx + dx + dy;       // (x+1, y+1)

    const float4 r00 = __ldg((const float4*)(image + i00));
    const float4 r01 = __ldg((const float4*)(image + i01));
    const float4 r10 = __ldg((const float4*)(image + i10));
    const float4 r11 = __ldg((const float4*)(image + i11));

    // 5th element (z = zb+4) of each row; at zb==124 the z=127 voxel's +1
    // neighbor is weight-masked, reuse last value.
    const bool last = (zb == 124);
    const float e00 = last ? r00.w : __ldg(image + i00 + 4);
    const float e01 = last ? r01.w : __ldg(image + i01 + 4);
    const float e10 = last ? r10.w : __ldg(image + i10 + 4);
    const float e11 = last ? r11.w : __ldg(image + i11 + 4);

    const float a00[5] = {r00.x, r00.y, r00.z, r00.w, e00};
    const float a01[5] = {r01.x, r01.y, r01.z, r01.w, e01};
    const float a10[5] = {r10.x, r10.y, r10.z, r10.w, e10};
    const float a11[5] = {r11.x, r11.y, r11.z, r11.w, e11};

    #pragma unroll
    for (int j = 0; j < 4; j++) {
        uint4 p;
        p.x = pack_h2(a00[j], a00[j + 1]);   // c111, c112
        p.y = pack_h2(a01[j], a01[j + 1]);   // c121, c122
        p.z = pack_h2(a10[j], a10[j + 1]);   // c211, c212
        p.w = pack_h2(a11[j], a11[j + 1]);   // c221, c222
        g_packed[idx + j] = p;
    }
}

__device__ __forceinline__ float sample_one(float gx, float gy, float gz, int base_b)
{
    const float x = fminf(fmaxf(gx * 128.0f, CLAMP_LO), CLAMP_HI);
    const float y = fminf(fmaxf(gy * 128.0f, CLAMP_LO), CLAMP_HI);
    const float z = fminf(fmaxf(gz * 128.0f, CLAMP_LO), CLAMP_HI);

    const float x1f = floorf(x), x2f = ceilf(x);
    const float y1f = floorf(y), y2f = ceilf(y);
    const float z1f = floorf(z), z2f = ceilf(z);

    const int cube = base_b + (((int)x1f) << 14) + (((int)y1f) << 7) + (int)z1f;
    const uint4 p = __ldg(&g_packed[cube]);

    const float2 a1 = __half22float2(*reinterpret_cast<const __half2*>(&p.x)); // c111,c112
    const float2 a2 = __half22float2(*reinterpret_cast<const __half2*>(&p.y)); // c121,c122
    const float2 b1 = __half22float2(*reinterpret_cast<const __half2*>(&p.z)); // c211,c212
    const float2 b2 = __half22float2(*reinterpret_cast<const __half2*>(&p.w)); // c221,c222

    const float wx = x - x1f, wx2 = x2f - x;
    const float wy = y - y1f, wy2 = y2f - y;
    const float wz = z - z1f, wz2 = z2f - z;

    const float lerp_y1 = (b1.x * wx + a1.x * wx2) * wy2
                        + (b2.x * wx + a2.x * wx2) * wy;
    const float lerp_y2 = (b1.y * wx + a1.y * wx2) * wy2
                        + (b2.y * wx + a2.y * wx2) * wy;
    return lerp_y2 * wz + lerp_y1 * wz2;
}

__global__ void __launch_bounds__(256)
trilinear_kernel(const float* __restrict__ grid,
                 float* __restrict__ out)
{
    const int t = blockIdx.x * blockDim.x + threadIdx.x;     // 4 samples per thread
    const int s = t << 2;                                    // first sample id
    const int base_b = (s >> 21) << 21;                      // batch base (4 samples same batch)

    const float4* g = (const float4*)(grid + 3 * (size_t)s); // 48 B, 16B-aligned
    const float4 g0 = __ldg(g + 0);   // x0 y0 z0 x1
    const float4 g1 = __ldg(g + 1);   // y1 z1 x2 y2
    const float4 g2 = __ldg(g + 2);   // z2 x3 y3 z3

    float4 r;
    r.x = sample_one(g0.x, g0.y, g0.z, base_b);
    r.y = sample_one(g0.w, g1.x, g1.y, base_b);
    r.z = sample_one(g1.z, g1.w, g2.x, base_b);
    r.w = sample_one(g2.y, g2.z, g2.w, base_b);

    *(float4*)(out + s) = r;
}

extern "C" void kernel_launch(void* const* d_in, const int* in_sizes, int n_in,
                              void* d_out, int out_size)
{
    const float* image = (const float*)d_in[0];
    const float* grid  = (const float*)d_in[1];
    float* out = (float*)d_out;

    pack_kernel<<<(VOXELS / 4) / 256, 256>>>(image);
    trilinear_kernel<<<(BATCH * NPTS / 4) / 256, 256>>>(grid, out);
}

// round 5
// speedup vs baseline: 1.2283x; 1.2283x over previous
#include <cuda_runtime.h>
#include <cuda_fp16.h>
#include <cstdint>

// ImageWarped: trilinear sampling of [B,128,128,128,1] fp32 at [B,N,3] coords.
// B=2, N=2097152.
//
// Phase 1 (pack, R3 form): per voxel pack the 2x2x2 corner cube as 8 x fp16
//   in one uint4 (64 MB scratch).
// Phase 2 (sample): ONE scattered LDG.128 per sample; 2 samples/thread.
//   Streaming traffic (grid reads, out writes) uses evict-first hints
//   (__ldcs/__stcs) so the 64 MB packed volume stays resident in the
//   126 MB L2 -> gather misses to DRAM drop, subsystems overlap better.
//
// fp16 corner quantization -> aggregate rel_err ~2e-4 (verified R3/R4).
// Boundary-clamped "+1" entries are weight-masked (exactly-zero fractional
// weights per the reference floor/ceil convention).

#define BATCH 2
#define NPTS  2097152
#define VOXELS (BATCH * 128 * 128 * 128)   // 4194304
#define CLAMP_LO 0.001f
#define CLAMP_HI 126.999f                  // min(SIZE) - 1.001

__device__ uint4 g_packed[VOXELS];         // 64 MB scratch: 8 fp16 per voxel

__device__ __forceinline__ uint32_t pack_h2(float a, float b) {
    __half2 h = __floats2half2_rn(a, b);
    return *reinterpret_cast<uint32_t*>(&h);
}

__global__ void __launch_bounds__(256)
pack_kernel(const float* __restrict__ image)
{
    const int idx = blockIdx.x * blockDim.x + threadIdx.x;   // (b,x,y,z) linear
    const int z = idx & 127;
    const int y = (idx >> 7) & 127;
    const int x = (idx >> 14) & 127;
    const int dz = (z < 127) ? 1 : 0;
    const int dy = (y < 127) ? 128 : 0;
    const int dx = (x < 127) ? 16384 : 0;

    const float c111 = __ldg(image + idx);
    const float c112 = __ldg(image + idx + dz);
    const float c121 = __ldg(image + idx + dy);
    const float c122 = __ldg(image + idx + dy + dz);
    const float c211 = __ldg(image + idx + dx);
    const float c212 = __ldg(image + idx + dx + dz);
    const float c221 = __ldg(image + idx + dx + dy);
    const float c222 = __ldg(image + idx + dx + dy + dz);

    uint4 p;
    p.x = pack_h2(c111, c112);
    p.y = pack_h2(c121, c122);
    p.z = pack_h2(c211, c212);
    p.w = pack_h2(c221, c222);
    g_packed[idx] = p;                       // default policy: allocate in L2
}

__device__ __forceinline__ float sample_one(float gx, float gy, float gz, int base_b)
{
    const float x = fminf(fmaxf(gx * 128.0f, CLAMP_LO), CLAMP_HI);
    const float y = fminf(fmaxf(gy * 128.0f, CLAMP_LO), CLAMP_HI);
    const float z = fminf(fmaxf(gz * 128.0f, CLAMP_LO), CLAMP_HI);

    const float x1f = floorf(x), x2f = ceilf(x);
    const float y1f = floorf(y), y2f = ceilf(y);
    const float z1f = floorf(z), z2f = ceilf(z);

    const int cube = base_b + (((int)x1f) << 14) + (((int)y1f) << 7) + (int)z1f;
    const uint4 p = __ldg(&g_packed[cube]);  // one 128-bit scattered gather

    const float2 a1 = __half22float2(*reinterpret_cast<const __half2*>(&p.x)); // c111,c112
    const float2 a2 = __half22float2(*reinterpret_cast<const __half2*>(&p.y)); // c121,c122
    const float2 b1 = __half22float2(*reinterpret_cast<const __half2*>(&p.z)); // c211,c212
    const float2 b2 = __half22float2(*reinterpret_cast<const __half2*>(&p.w)); // c221,c222

    const float wx = x - x1f, wx2 = x2f - x;
    const float wy = y - y1f, wy2 = y2f - y;
    const float wz = z - z1f, wz2 = z2f - z;

    const float lerp_y1 = (b1.x * wx + a1.x * wx2) * wy2
                        + (b2.x * wx + a2.x * wx2) * wy;
    const float lerp_y2 = (b1.y * wx + a1.y * wx2) * wy2
                        + (b2.y * wx + a2.y * wx2) * wy;
    return lerp_y2 * wz + lerp_y1 * wz2;
}

__global__ void __launch_bounds__(256)
trilinear_kernel(const float* __restrict__ grid,
                 float* __restrict__ out)
{
    const int t = blockIdx.x * blockDim.x + threadIdx.x;     // 2 samples per thread
    const int s = t << 1;                                    // first sample id
    const int base_b = (s >> 21) << 21;                      // batch base (pair same batch)

    // grid floats for samples s, s+1: g[0..5]; 8-byte aligned (24 B * t)
    const float2* g = (const float2*)(grid + 3 * (size_t)s);
    const float2 q0 = __ldcs(g + 0);   // x0 y0
    const float2 q1 = __ldcs(g + 1);   // z0 x1
    const float2 q2 = __ldcs(g + 2);   // y1 z1

    float2 r;
    r.x = sample_one(q0.x, q0.y, q1.x, base_b);
    r.y = sample_one(q1.y, q2.x, q2.y, base_b);

    __stcs((float2*)(out + s), r);     // evict-first: don't pollute L2
}

extern "C" void kernel_launch(void* const* d_in, const int* in_sizes, int n_in,
                              void* d_out, int out_size)
{
    const float* image = (const float*)d_in[0];
    const float* grid  = (const float*)d_in[1];
    float* out = (float*)d_out;

    pack_kernel<<<VOXELS / 256, 256>>>(image);
    trilinear_kernel<<<(BATCH * NPTS / 2) / 256, 256>>>(grid, out);
}